// round 4
// baseline (speedup 1.0000x reference)
#include <cuda_runtime.h>

#define NND 100000
#define NE  1250000
#define HID 64
#define SROW 68
#define CSR_BLOCKS 98
#define CSR_THREADS 1024

// ---------------- scratch (device globals; no allocation allowed) ----------
__device__ float g_h0[NND * HID];
__device__ float g_h1[NND * HID];
__device__ float g_agg[NND * HID];
__device__ int   g_cnt[NND];
__device__ int   g_rowstart[NND];
__device__ int   g_cursor[NND];
__device__ int   g_adj[NE];
__device__ int   g_blocksum[CSR_BLOCKS];
__device__ int   g_bar_count;
__device__ int   g_bar_sense;

typedef unsigned long long ull;
union F4U { float4 f; ull u[2]; };

__device__ __forceinline__ ull pack2(float v) {
    ull r; asm("mov.b64 %0, {%1, %1};" : "=l"(r) : "f"(v)); return r;
}
__device__ __forceinline__ void fma2(ull& d, ull a, ull b) {
    asm("fma.rn.f32x2 %0, %1, %2, %0;" : "+l"(d) : "l"(a), "l"(b));
}
__device__ __forceinline__ float2 unpk(ull v) {
    float2 r; asm("mov.b64 {%0, %1}, %2;" : "=f"(r.x), "=f"(r.y) : "l"(v)); return r;
}
__device__ __forceinline__ float prelu(float v, float a) { return v >= 0.f ? v : a * v; }

// ---------------- launch 1: zero cnt + reset barrier + embedding gather -----
__global__ void prep_kernel(const int* __restrict__ x,
                            const float* __restrict__ emb,
                            float* __restrict__ h0) {
    int t = blockIdx.x * blockDim.x + threadIdx.x;
    if (t < NND) g_cnt[t] = 0;
    if (t == 0) { g_bar_count = 0; g_bar_sense = 0; }
    int i = t >> 4;
    int p = (t & 15) << 2;
    int xi = __ldg(&x[i]);
    *(float4*)&h0[i * HID + p] = *(const float4*)&emb[xi * HID + p];
}

// ---------------- software grid barrier -------------------------------------
__device__ __forceinline__ void grid_barrier(int phase) {
    __threadfence();
    __syncthreads();
    if (threadIdx.x == 0) {
        int v = atomicAdd(&g_bar_count, 1);
        if (v == CSR_BLOCKS - 1) {
            atomicExch(&g_bar_count, 0);
            __threadfence();
            atomicExch(&g_bar_sense, phase);
        } else {
            while (true) {
                int s;
                asm volatile("ld.global.cg.s32 %0, [%1];" : "=r"(s) : "l"(&g_bar_sense));
                if (s >= phase) break;
                __nanosleep(64);
            }
        }
    }
    __syncthreads();
}

// ---------------- launch 2: persistent CSR build ----------------------------
__global__ __launch_bounds__(CSR_THREADS) void csr_kernel(const int* __restrict__ ei) {
    const int tid = threadIdx.x, bid = blockIdx.x;
    const int gid = bid * CSR_THREADS + tid;
    const int gstride = CSR_BLOCKS * CSR_THREADS;

    for (int e = gid; e < NE; e += gstride)
        atomicAdd(&g_cnt[__ldg(&ei[NE + e])], 1);
    grid_barrier(1);

    __shared__ int swarp[32];
    __shared__ int soff[CSR_BLOCKS];
    int v = 0;
    if (gid < NND)
        asm volatile("ld.global.cg.s32 %0, [%1];" : "=r"(v) : "l"(&g_cnt[gid]));
    const int lane = tid & 31, wid = tid >> 5;
    int x = v;
    #pragma unroll
    for (int d = 1; d < 32; d <<= 1) { int t = __shfl_up_sync(~0u, x, d); if (lane >= d) x += t; }
    if (lane == 31) swarp[wid] = x;
    __syncthreads();
    if (wid == 0) {
        int y = swarp[lane];
        int z = y;
        #pragma unroll
        for (int d = 1; d < 32; d <<= 1) { int t = __shfl_up_sync(~0u, z, d); if (lane >= d) z += t; }
        swarp[lane] = z - y;
    }
    __syncthreads();
    const int excl = x - v + swarp[wid];
    if (tid == CSR_THREADS - 1) g_blocksum[bid] = excl + v;
    grid_barrier(2);

    if (tid < CSR_BLOCKS) {
        int b;
        asm volatile("ld.global.cg.s32 %0, [%1];" : "=r"(b) : "l"(&g_blocksum[tid]));
        soff[tid] = b;
    }
    __syncthreads();
    if (tid == 0) {
        int run = 0;
        for (int i = 0; i < CSR_BLOCKS; i++) { int t = soff[i]; soff[i] = run; run += t; }
    }
    __syncthreads();
    if (gid < NND) {
        int st = excl + soff[bid];
        g_rowstart[gid] = st;
        g_cursor[gid] = st;
    }
    grid_barrier(3);

    for (int e = gid; e < NE; e += gstride) {
        int src = __ldg(&ei[e]);
        int dst = __ldg(&ei[NE + e]);
        int pp = atomicAdd(&g_cursor[dst], 1);
        g_adj[pp] = src;
    }
}

// ---------------- mean aggregation (lean, high-occupancy) -------------------
// one node per 16-lane group; adj batch via shfl; unroll-4 row gathers
__global__ __launch_bounds__(256) void agg_kernel(const float* __restrict__ h,
                                                  float* __restrict__ aggout) {
    const int tid = threadIdx.x;
    const int gid = blockIdx.x * 256 + tid;
    const int node = gid >> 4;
    if (node >= NND) return;
    const int lane16 = tid & 15;
    const int p4 = lane16 << 2;
    const unsigned smask = 0xFFFFu << (tid & 16);

    const int st = __ldg(&g_rowstart[node]);
    const int n  = __ldg(&g_cnt[node]);
    float4 acc = make_float4(0.f, 0.f, 0.f, 0.f);
    for (int j = 0; j < n; j += 16) {
        const int m = min(16, n - j);
        int idx = 0;
        if (lane16 < m) idx = __ldg(&g_adj[st + j + lane16]);
        int jj = 0;
        for (; jj + 4 <= m; jj += 4) {
            int s0 = __shfl_sync(smask, idx, jj + 0, 16);
            int s1 = __shfl_sync(smask, idx, jj + 1, 16);
            int s2 = __shfl_sync(smask, idx, jj + 2, 16);
            int s3 = __shfl_sync(smask, idx, jj + 3, 16);
            float4 v0 = *(const float4*)&h[s0 * HID + p4];
            float4 v1 = *(const float4*)&h[s1 * HID + p4];
            float4 v2 = *(const float4*)&h[s2 * HID + p4];
            float4 v3 = *(const float4*)&h[s3 * HID + p4];
            acc.x += (v0.x + v1.x) + (v2.x + v3.x);
            acc.y += (v0.y + v1.y) + (v2.y + v3.y);
            acc.z += (v0.z + v1.z) + (v2.z + v3.z);
            acc.w += (v0.w + v1.w) + (v2.w + v3.w);
        }
        for (; jj < m; jj++) {
            int s0 = __shfl_sync(smask, idx, jj, 16);
            float4 v0 = *(const float4*)&h[s0 * HID + p4];
            acc.x += v0.x; acc.y += v0.y; acc.z += v0.z; acc.w += v0.w;
        }
    }
    const float iv = 1.0f / (float)max(n, 1);
    *(float4*)&aggout[node * HID + p4] =
        make_float4(acc.x * iv, acc.y * iv, acc.z * iv, acc.w * iv);
}

// ---------------- dual GEMM: out = mean@Wl + h@Wr + bl, PReLU ----------------
// chunk = 64 nodes; thread = 2 nodes x 8 cols; FMA2-dense, minimal LDS
__global__ __launch_bounds__(256) void gemm_dual_kernel(
    const float* __restrict__ h, const float* __restrict__ agg,
    const float* __restrict__ Wl, const float* __restrict__ bl,
    const float* __restrict__ Wr, const float* __restrict__ alpha_p,
    float* __restrict__ out)
{
    __shared__ float sWl[HID * HID];
    __shared__ float sWr[HID * HID];
    __shared__ float sb[HID];
    __shared__ float srm[64 * SROW];
    __shared__ float srh[64 * SROW];

    const int tid = threadIdx.x;
    for (int i = tid; i < HID * HID; i += 256) { sWl[i] = Wl[i]; sWr[i] = Wr[i]; }
    if (tid < HID) sb[tid] = bl[tid];
    const float alpha = __ldg(alpha_p);
    __syncthreads();

    const int cb = (tid & 7) << 3;       // col base (8 cols)
    const int rA = (tid >> 3) << 1;      // node pair within chunk
    const int rB = rA + 1;
    const int nchunks = (NND + 63) / 64; // 1563

    for (int chunk = blockIdx.x; chunk < nchunks; chunk += gridDim.x) {
        const int base = chunk * 64;

        #pragma unroll
        for (int t = tid; t < 64 * HID; t += 256) {
            int r = t >> 6, k = t & 63;
            int node = base + r;
            float hv = 0.f, mv = 0.f;
            if (node < NND) { hv = h[node * HID + k]; mv = agg[node * HID + k]; }
            srh[r * SROW + k] = hv;
            srm[r * SROW + k] = mv;
        }
        __syncthreads();

        F4U b0, b1;
        b0.f = *(const float4*)&sb[cb];
        b1.f = *(const float4*)&sb[cb + 4];
        ull a[4] = { b0.u[0], b0.u[1], b1.u[0], b1.u[1] };
        ull b[4] = { b0.u[0], b0.u[1], b1.u[0], b1.u[1] };

        #pragma unroll
        for (int k = 0; k < HID; k++) {
            F4U w10, w11, w20, w21;
            w10.f = *(const float4*)&sWl[k * HID + cb];
            w11.f = *(const float4*)&sWl[k * HID + cb + 4];
            w20.f = *(const float4*)&sWr[k * HID + cb];
            w21.f = *(const float4*)&sWr[k * HID + cb + 4];
            ull mA = pack2(srm[rA * SROW + k]);
            ull hA = pack2(srh[rA * SROW + k]);
            ull mB = pack2(srm[rB * SROW + k]);
            ull hB = pack2(srh[rB * SROW + k]);
            fma2(a[0], mA, w10.u[0]); fma2(a[1], mA, w10.u[1]);
            fma2(a[2], mA, w11.u[0]); fma2(a[3], mA, w11.u[1]);
            fma2(a[0], hA, w20.u[0]); fma2(a[1], hA, w20.u[1]);
            fma2(a[2], hA, w21.u[0]); fma2(a[3], hA, w21.u[1]);
            fma2(b[0], mB, w10.u[0]); fma2(b[1], mB, w10.u[1]);
            fma2(b[2], mB, w11.u[0]); fma2(b[3], mB, w11.u[1]);
            fma2(b[0], hB, w20.u[0]); fma2(b[1], hB, w20.u[1]);
            fma2(b[2], hB, w21.u[0]); fma2(b[3], hB, w21.u[1]);
        }

        const int nodeA = base + rA, nodeB = base + rB;
        if (nodeA < NND) {
            float2 p0 = unpk(a[0]), p1 = unpk(a[1]), p2 = unpk(a[2]), p3 = unpk(a[3]);
            *(float4*)&out[nodeA * HID + cb] =
                make_float4(prelu(p0.x, alpha), prelu(p0.y, alpha),
                            prelu(p1.x, alpha), prelu(p1.y, alpha));
            *(float4*)&out[nodeA * HID + cb + 4] =
                make_float4(prelu(p2.x, alpha), prelu(p2.y, alpha),
                            prelu(p3.x, alpha), prelu(p3.y, alpha));
        }
        if (nodeB < NND) {
            float2 p0 = unpk(b[0]), p1 = unpk(b[1]), p2 = unpk(b[2]), p3 = unpk(b[3]);
            *(float4*)&out[nodeB * HID + cb] =
                make_float4(prelu(p0.x, alpha), prelu(p0.y, alpha),
                            prelu(p1.x, alpha), prelu(p1.y, alpha));
            *(float4*)&out[nodeB * HID + cb + 4] =
                make_float4(prelu(p2.x, alpha), prelu(p2.y, alpha),
                            prelu(p3.x, alpha), prelu(p3.y, alpha));
        }
        __syncthreads();
    }
}

// ---------------- single GEMM: out = h @ W + b -------------------------------
__global__ __launch_bounds__(256) void gemm_single_kernel(
    const float* __restrict__ h,
    const float* __restrict__ W, const float* __restrict__ bb,
    float* __restrict__ out)
{
    __shared__ float sW[HID * HID];
    __shared__ float sb[HID];
    __shared__ float srh[64 * SROW];

    const int tid = threadIdx.x;
    for (int i = tid; i < HID * HID; i += 256) sW[i] = W[i];
    if (tid < HID) sb[tid] = bb[tid];
    __syncthreads();

    const int cb = (tid & 7) << 3;
    const int rA = (tid >> 3) << 1;
    const int rB = rA + 1;
    const int nchunks = (NND + 63) / 64;

    for (int chunk = blockIdx.x; chunk < nchunks; chunk += gridDim.x) {
        const int base = chunk * 64;
        #pragma unroll
        for (int t = tid; t < 64 * HID; t += 256) {
            int r = t >> 6, k = t & 63;
            int node = base + r;
            srh[r * SROW + k] = (node < NND) ? h[node * HID + k] : 0.f;
        }
        __syncthreads();

        F4U b0, b1;
        b0.f = *(const float4*)&sb[cb];
        b1.f = *(const float4*)&sb[cb + 4];
        ull a[4] = { b0.u[0], b0.u[1], b1.u[0], b1.u[1] };
        ull b[4] = { b0.u[0], b0.u[1], b1.u[0], b1.u[1] };

        #pragma unroll
        for (int k = 0; k < HID; k++) {
            F4U w0, w1;
            w0.f = *(const float4*)&sW[k * HID + cb];
            w1.f = *(const float4*)&sW[k * HID + cb + 4];
            ull vA = pack2(srh[rA * SROW + k]);
            ull vB = pack2(srh[rB * SROW + k]);
            fma2(a[0], vA, w0.u[0]); fma2(a[1], vA, w0.u[1]);
            fma2(a[2], vA, w1.u[0]); fma2(a[3], vA, w1.u[1]);
            fma2(b[0], vB, w0.u[0]); fma2(b[1], vB, w0.u[1]);
            fma2(b[2], vB, w1.u[0]); fma2(b[3], vB, w1.u[1]);
        }

        const int nodeA = base + rA, nodeB = base + rB;
        if (nodeA < NND) {
            float2 p0 = unpk(a[0]), p1 = unpk(a[1]), p2 = unpk(a[2]), p3 = unpk(a[3]);
            *(float4*)&out[nodeA * HID + cb]     = make_float4(p0.x, p0.y, p1.x, p1.y);
            *(float4*)&out[nodeA * HID + cb + 4] = make_float4(p2.x, p2.y, p3.x, p3.y);
        }
        if (nodeB < NND) {
            float2 p0 = unpk(b[0]), p1 = unpk(b[1]), p2 = unpk(b[2]), p3 = unpk(b[3]);
            *(float4*)&out[nodeB * HID + cb]     = make_float4(p0.x, p0.y, p1.x, p1.y);
            *(float4*)&out[nodeB * HID + cb + 4] = make_float4(p2.x, p2.y, p3.x, p3.y);
        }
        __syncthreads();
    }
}

// ---------------- launch -----------------------------------------------------
extern "C" void kernel_launch(void* const* d_in, const int* in_sizes, int n_in,
                              void* d_out, int out_size) {
    const int*   x    = (const int*)d_in[0];
    const int*   ei   = (const int*)d_in[1];
    // d_in[2] = edge_weight : unused by the reference
    const float* emb  = (const float*)d_in[3];
    const float* Wl1  = (const float*)d_in[4];
    const float* bl1  = (const float*)d_in[5];
    const float* Wr1  = (const float*)d_in[6];
    const float* a1   = (const float*)d_in[7];
    const float* Wl2  = (const float*)d_in[8];
    const float* bl2  = (const float*)d_in[9];
    const float* Wr2  = (const float*)d_in[10];
    const float* a2   = (const float*)d_in[11];
    const float* Wout = (const float*)d_in[12];
    const float* bout = (const float*)d_in[13];
    float* out = (float*)d_out;

    float *h0, *h1, *agg;
    cudaGetSymbolAddress((void**)&h0,  g_h0);
    cudaGetSymbolAddress((void**)&h1,  g_h1);
    cudaGetSymbolAddress((void**)&agg, g_agg);

    const int g_agg_grid = (NND * 16 + 255) / 256;   // 6250

    prep_kernel<<<g_agg_grid, 256>>>(x, emb, h0);
    csr_kernel<<<CSR_BLOCKS, CSR_THREADS>>>(ei);

    // layer 1
    agg_kernel<<<g_agg_grid, 256>>>(h0, agg);
    gemm_dual_kernel<<<444, 256>>>(h0, agg, Wl1, bl1, Wr1, a1, h1);

    // layer 2
    agg_kernel<<<g_agg_grid, 256>>>(h1, agg);
    gemm_dual_kernel<<<444, 256>>>(h1, agg, Wl2, bl2, Wr2, a2, h0);

    // output projection
    gemm_single_kernel<<<888, 256>>>(h0, Wout, bout, out);
}

// round 5
// speedup vs baseline: 1.3892x; 1.3892x over previous
#include <cuda_runtime.h>

#define NND 100000
#define NE  1250000
#define HID 64
#define CSR_BLOCKS 98
#define CSR_THREADS 1024

#define WST 68            // sW row stride (floats)
#define AST 132           // sA row stride for K=128 (floats)
#define AST1 68           // sA row stride for K=64

// ---------------- scratch (device globals; no allocation allowed) ----------
__device__ float g_h0[NND * HID];
__device__ float g_h1[NND * HID];
__device__ float g_agg[NND * HID];
__device__ int   g_cnt[NND];
__device__ int   g_rowstart[NND];
__device__ int   g_cursor[NND];
__device__ int   g_adj[NE];
__device__ int   g_blocksum[CSR_BLOCKS];
__device__ int   g_bar_count;
__device__ int   g_bar_sense;

typedef unsigned long long ull;
union F4U { float4 f; ull u[2]; };

__device__ __forceinline__ ull pack2(float v) {
    ull r; asm("mov.b64 %0, {%1, %1};" : "=l"(r) : "f"(v)); return r;
}
__device__ __forceinline__ void fma2(ull& d, ull a, ull b) {
    asm("fma.rn.f32x2 %0, %1, %2, %0;" : "+l"(d) : "l"(a), "l"(b));
}
__device__ __forceinline__ float2 unpk(ull v) {
    float2 r; asm("mov.b64 {%0, %1}, %2;" : "=f"(r.x), "=f"(r.y) : "l"(v)); return r;
}
__device__ __forceinline__ float prelu(float v, float a) { return v >= 0.f ? v : a * v; }
__device__ __forceinline__ float comp4(float4 v, int kk) {
    return kk == 0 ? v.x : (kk == 1 ? v.y : (kk == 2 ? v.z : v.w));
}

// ---------------- launch 1: zero cnt + reset barrier + embedding gather -----
__global__ void prep_kernel(const int* __restrict__ x,
                            const float* __restrict__ emb,
                            float* __restrict__ h0) {
    int t = blockIdx.x * blockDim.x + threadIdx.x;
    if (t < NND) g_cnt[t] = 0;
    if (t == 0) { g_bar_count = 0; g_bar_sense = 0; }
    int i = t >> 4;
    int p = (t & 15) << 2;
    int xi = __ldg(&x[i]);
    *(float4*)&h0[i * HID + p] = *(const float4*)&emb[xi * HID + p];
}

// ---------------- software grid barrier -------------------------------------
__device__ __forceinline__ void grid_barrier(int phase) {
    __threadfence();
    __syncthreads();
    if (threadIdx.x == 0) {
        int v = atomicAdd(&g_bar_count, 1);
        if (v == CSR_BLOCKS - 1) {
            atomicExch(&g_bar_count, 0);
            __threadfence();
            atomicExch(&g_bar_sense, phase);
        } else {
            while (true) {
                int s;
                asm volatile("ld.global.cg.s32 %0, [%1];" : "=r"(s) : "l"(&g_bar_sense));
                if (s >= phase) break;
                __nanosleep(64);
            }
        }
    }
    __syncthreads();
}

// ---------------- launch 2: persistent CSR build ----------------------------
__global__ __launch_bounds__(CSR_THREADS) void csr_kernel(const int* __restrict__ ei) {
    const int tid = threadIdx.x, bid = blockIdx.x;
    const int gid = bid * CSR_THREADS + tid;
    const int gstride = CSR_BLOCKS * CSR_THREADS;

    for (int e = gid; e < NE; e += gstride)
        atomicAdd(&g_cnt[__ldg(&ei[NE + e])], 1);
    grid_barrier(1);

    __shared__ int swarp[32];
    __shared__ int soff[CSR_BLOCKS];
    int v = 0;
    if (gid < NND)
        asm volatile("ld.global.cg.s32 %0, [%1];" : "=r"(v) : "l"(&g_cnt[gid]));
    const int lane = tid & 31, wid = tid >> 5;
    int x = v;
    #pragma unroll
    for (int d = 1; d < 32; d <<= 1) { int t = __shfl_up_sync(~0u, x, d); if (lane >= d) x += t; }
    if (lane == 31) swarp[wid] = x;
    __syncthreads();
    if (wid == 0) {
        int y = swarp[lane];
        int z = y;
        #pragma unroll
        for (int d = 1; d < 32; d <<= 1) { int t = __shfl_up_sync(~0u, z, d); if (lane >= d) z += t; }
        swarp[lane] = z - y;
    }
    __syncthreads();
    const int excl = x - v + swarp[wid];
    if (tid == CSR_THREADS - 1) g_blocksum[bid] = excl + v;
    grid_barrier(2);

    if (tid < CSR_BLOCKS) {
        int b;
        asm volatile("ld.global.cg.s32 %0, [%1];" : "=r"(b) : "l"(&g_blocksum[tid]));
        soff[tid] = b;
    }
    __syncthreads();
    if (tid == 0) {
        int run = 0;
        for (int i = 0; i < CSR_BLOCKS; i++) { int t = soff[i]; soff[i] = run; run += t; }
    }
    __syncthreads();
    if (gid < NND) {
        int st = excl + soff[bid];
        g_rowstart[gid] = st;
        g_cursor[gid] = st;
    }
    grid_barrier(3);

    for (int e = gid; e < NE; e += gstride) {
        int src = __ldg(&ei[e]);
        int dst = __ldg(&ei[NE + e]);
        int pp = atomicAdd(&g_cursor[dst], 1);
        g_adj[pp] = src;
    }
}

// ---------------- mean aggregation (lean, high-occupancy) -------------------
__global__ __launch_bounds__(256) void agg_kernel(const float* __restrict__ h,
                                                  float* __restrict__ aggout) {
    const int tid = threadIdx.x;
    const int gid = blockIdx.x * 256 + tid;
    const int node = gid >> 4;
    if (node >= NND) return;
    const int lane16 = tid & 15;
    const int p4 = lane16 << 2;
    const unsigned smask = 0xFFFFu << (tid & 16);

    const int st = __ldg(&g_rowstart[node]);
    const int n  = __ldg(&g_cnt[node]);
    float4 acc = make_float4(0.f, 0.f, 0.f, 0.f);
    for (int j = 0; j < n; j += 16) {
        const int m = min(16, n - j);
        int idx = 0;
        if (lane16 < m) idx = __ldg(&g_adj[st + j + lane16]);
        int jj = 0;
        for (; jj + 4 <= m; jj += 4) {
            int s0 = __shfl_sync(smask, idx, jj + 0, 16);
            int s1 = __shfl_sync(smask, idx, jj + 1, 16);
            int s2 = __shfl_sync(smask, idx, jj + 2, 16);
            int s3 = __shfl_sync(smask, idx, jj + 3, 16);
            float4 v0 = *(const float4*)&h[s0 * HID + p4];
            float4 v1 = *(const float4*)&h[s1 * HID + p4];
            float4 v2 = *(const float4*)&h[s2 * HID + p4];
            float4 v3 = *(const float4*)&h[s3 * HID + p4];
            acc.x += (v0.x + v1.x) + (v2.x + v3.x);
            acc.y += (v0.y + v1.y) + (v2.y + v3.y);
            acc.z += (v0.z + v1.z) + (v2.z + v3.z);
            acc.w += (v0.w + v1.w) + (v2.w + v3.w);
        }
        for (; jj < m; jj++) {
            int s0 = __shfl_sync(smask, idx, jj, 16);
            float4 v0 = *(const float4*)&h[s0 * HID + p4];
            acc.x += v0.x; acc.y += v0.y; acc.z += v0.z; acc.w += v0.w;
        }
    }
    const float iv = 1.0f / (float)max(n, 1);
    *(float4*)&aggout[node * HID + p4] =
        make_float4(acc.x * iv, acc.y * iv, acc.z * iv, acc.w * iv);
}

// ---------------- dual GEMM as single K=128 GEMM -----------------------------
// chunk = 128 nodes; thread = 4 nodes x 8 cols register tile.
// smem: sW[128][WST], sb[64], sA[128][AST]  (dynamic, ~100KB, 2 CTAs/SM)
__global__ __launch_bounds__(256, 2) void gemm_dual_kernel(
    const float* __restrict__ h, const float* __restrict__ agg,
    const float* __restrict__ Wl, const float* __restrict__ bl,
    const float* __restrict__ Wr, const float* __restrict__ alpha_p,
    float* __restrict__ out)
{
    extern __shared__ float sm[];
    float* sW = sm;                        // 128*WST
    float* sb = sW + 128 * WST;            // 64
    float* sA = sb + 64;                   // 128*AST

    const int tid = threadIdx.x;
    // stage stacked weights: k<64 -> Wl, k>=64 -> Wr
    #pragma unroll
    for (int t = tid; t < 128 * 16; t += 256) {       // 128 rows x 16 float4
        int k = t >> 4, q = (t & 15) << 2;
        float4 w = (k < 64) ? *(const float4*)&Wl[k * HID + q]
                            : *(const float4*)&Wr[(k - 64) * HID + q];
        *(float4*)&sW[k * WST + q] = w;
    }
    if (tid < HID) sb[tid] = bl[tid];
    const float alpha = __ldg(alpha_p);

    const int cb = (tid & 7) << 3;          // 8 output cols
    const int r0 = (tid >> 3) << 2;         // 4 node rows
    const int nchunks = (NND + 127) / 128;  // 782

    for (int chunk = blockIdx.x; chunk < nchunks; chunk += gridDim.x) {
        const int base = chunk * 128;
        __syncthreads();
        // stage sA: row r = [mean(64) | h(64)]
        #pragma unroll
        for (int t = tid; t < 128 * 32; t += 256) {   // 128 rows x 32 float4
            int r = t >> 5, kq = (t & 31) << 2;
            int node = base + r;
            float4 v = make_float4(0.f, 0.f, 0.f, 0.f);
            if (node < NND)
                v = (kq < 64) ? *(const float4*)&agg[node * HID + kq]
                              : *(const float4*)&h[node * HID + kq - 64];
            *(float4*)&sA[r * AST + kq] = v;
        }
        __syncthreads();

        F4U b0, b1;
        b0.f = *(const float4*)&sb[cb];
        b1.f = *(const float4*)&sb[cb + 4];
        ull acc[4][4];
        #pragma unroll
        for (int i = 0; i < 4; i++) {
            acc[i][0] = b0.u[0]; acc[i][1] = b0.u[1];
            acc[i][2] = b1.u[0]; acc[i][3] = b1.u[1];
        }

        #pragma unroll 4
        for (int kb = 0; kb < 128; kb += 4) {
            float4 av[4];
            #pragma unroll
            for (int i = 0; i < 4; i++)
                av[i] = *(const float4*)&sA[(r0 + i) * AST + kb];
            #pragma unroll
            for (int kk = 0; kk < 4; kk++) {
                F4U w0, w1;
                w0.f = *(const float4*)&sW[(kb + kk) * WST + cb];
                w1.f = *(const float4*)&sW[(kb + kk) * WST + cb + 4];
                #pragma unroll
                for (int i = 0; i < 4; i++) {
                    ull ap = pack2(comp4(av[i], kk));
                    fma2(acc[i][0], ap, w0.u[0]);
                    fma2(acc[i][1], ap, w0.u[1]);
                    fma2(acc[i][2], ap, w1.u[0]);
                    fma2(acc[i][3], ap, w1.u[1]);
                }
            }
        }

        #pragma unroll
        for (int i = 0; i < 4; i++) {
            int node = base + r0 + i;
            if (node < NND) {
                float2 p0 = unpk(acc[i][0]), p1 = unpk(acc[i][1]);
                float2 p2 = unpk(acc[i][2]), p3 = unpk(acc[i][3]);
                *(float4*)&out[node * HID + cb] =
                    make_float4(prelu(p0.x, alpha), prelu(p0.y, alpha),
                                prelu(p1.x, alpha), prelu(p1.y, alpha));
                *(float4*)&out[node * HID + cb + 4] =
                    make_float4(prelu(p2.x, alpha), prelu(p2.y, alpha),
                                prelu(p3.x, alpha), prelu(p3.y, alpha));
            }
        }
    }
}

// ---------------- single GEMM: out = h @ W + b (K=64) ------------------------
__global__ __launch_bounds__(256, 3) void gemm_single_kernel(
    const float* __restrict__ h,
    const float* __restrict__ W, const float* __restrict__ bb,
    float* __restrict__ out)
{
    extern __shared__ float sm[];
    float* sW = sm;                        // 64*WST
    float* sb = sW + 64 * WST;             // 64
    float* sA = sb + 64;                   // 128*AST1

    const int tid = threadIdx.x;
    #pragma unroll
    for (int t = tid; t < 64 * 16; t += 256) {
        int k = t >> 4, q = (t & 15) << 2;
        *(float4*)&sW[k * WST + q] = *(const float4*)&W[k * HID + q];
    }
    if (tid < HID) sb[tid] = bb[tid];

    const int cb = (tid & 7) << 3;
    const int r0 = (tid >> 3) << 2;
    const int nchunks = (NND + 127) / 128;

    for (int chunk = blockIdx.x; chunk < nchunks; chunk += gridDim.x) {
        const int base = chunk * 128;
        __syncthreads();
        #pragma unroll
        for (int t = tid; t < 128 * 16; t += 256) {
            int r = t >> 4, kq = (t & 15) << 2;
            int node = base + r;
            float4 v = make_float4(0.f, 0.f, 0.f, 0.f);
            if (node < NND) v = *(const float4*)&h[node * HID + kq];
            *(float4*)&sA[r * AST1 + kq] = v;
        }
        __syncthreads();

        F4U b0, b1;
        b0.f = *(const float4*)&sb[cb];
        b1.f = *(const float4*)&sb[cb + 4];
        ull acc[4][4];
        #pragma unroll
        for (int i = 0; i < 4; i++) {
            acc[i][0] = b0.u[0]; acc[i][1] = b0.u[1];
            acc[i][2] = b1.u[0]; acc[i][3] = b1.u[1];
        }

        #pragma unroll 4
        for (int kb = 0; kb < 64; kb += 4) {
            float4 av[4];
            #pragma unroll
            for (int i = 0; i < 4; i++)
                av[i] = *(const float4*)&sA[(r0 + i) * AST1 + kb];
            #pragma unroll
            for (int kk = 0; kk < 4; kk++) {
                F4U w0, w1;
                w0.f = *(const float4*)&sW[(kb + kk) * WST + cb];
                w1.f = *(const float4*)&sW[(kb + kk) * WST + cb + 4];
                #pragma unroll
                for (int i = 0; i < 4; i++) {
                    ull ap = pack2(comp4(av[i], kk));
                    fma2(acc[i][0], ap, w0.u[0]);
                    fma2(acc[i][1], ap, w0.u[1]);
                    fma2(acc[i][2], ap, w1.u[0]);
                    fma2(acc[i][3], ap, w1.u[1]);
                }
            }
        }

        #pragma unroll
        for (int i = 0; i < 4; i++) {
            int node = base + r0 + i;
            if (node < NND) {
                float2 p0 = unpk(acc[i][0]), p1 = unpk(acc[i][1]);
                float2 p2 = unpk(acc[i][2]), p3 = unpk(acc[i][3]);
                *(float4*)&out[node * HID + cb]     = make_float4(p0.x, p0.y, p1.x, p1.y);
                *(float4*)&out[node * HID + cb + 4] = make_float4(p2.x, p2.y, p3.x, p3.y);
            }
        }
    }
}

// ---------------- launch -----------------------------------------------------
extern "C" void kernel_launch(void* const* d_in, const int* in_sizes, int n_in,
                              void* d_out, int out_size) {
    const int*   x    = (const int*)d_in[0];
    const int*   ei   = (const int*)d_in[1];
    // d_in[2] = edge_weight : unused by the reference
    const float* emb  = (const float*)d_in[3];
    const float* Wl1  = (const float*)d_in[4];
    const float* bl1  = (const float*)d_in[5];
    const float* Wr1  = (const float*)d_in[6];
    const float* a1   = (const float*)d_in[7];
    const float* Wl2  = (const float*)d_in[8];
    const float* bl2  = (const float*)d_in[9];
    const float* Wr2  = (const float*)d_in[10];
    const float* a2   = (const float*)d_in[11];
    const float* Wout = (const float*)d_in[12];
    const float* bout = (const float*)d_in[13];
    float* out = (float*)d_out;

    float *h0, *h1, *agg;
    cudaGetSymbolAddress((void**)&h0,  g_h0);
    cudaGetSymbolAddress((void**)&h1,  g_h1);
    cudaGetSymbolAddress((void**)&agg, g_agg);

    const size_t smem_dual   = (128 * WST + 64 + 128 * AST)  * sizeof(float); // ~100KB
    const size_t smem_single = (64 * WST  + 64 + 128 * AST1) * sizeof(float); // ~52KB
    cudaFuncSetAttribute(gemm_dual_kernel,
                         cudaFuncAttributeMaxDynamicSharedMemorySize, (int)smem_dual);
    cudaFuncSetAttribute(gemm_single_kernel,
                         cudaFuncAttributeMaxDynamicSharedMemorySize, (int)smem_single);

    const int g_agg_grid = (NND * 16) / 256;   // 6250

    prep_kernel<<<g_agg_grid, 256>>>(x, emb, h0);
    csr_kernel<<<CSR_BLOCKS, CSR_THREADS>>>(ei);

    // layer 1
    agg_kernel<<<g_agg_grid, 256>>>(h0, agg);
    gemm_dual_kernel<<<296, 256, smem_dual>>>(h0, agg, Wl1, bl1, Wr1, a1, h1);

    // layer 2
    agg_kernel<<<g_agg_grid, 256>>>(h1, agg);
    gemm_dual_kernel<<<296, 256, smem_dual>>>(h1, agg, Wl2, bl2, Wr2, a2, h0);

    // output projection
    gemm_single_kernel<<<444, 256, smem_single>>>(h0, Wout, bout, out);
}

// round 6
// speedup vs baseline: 1.6992x; 1.2231x over previous
#include <cuda_runtime.h>

#define NND 100000
#define NE  1250000
#define HID 64
#define CSR_BLOCKS 98
#define CSR_THREADS 1024

#define APSTRIDE 130   // sAp pair stride in ulls (K=128 + pad)
#define APSTRIDE1 66   // sAp pair stride for K=64

// ---------------- scratch (device globals; no allocation allowed) ----------
__device__ float g_h0[NND * HID];
__device__ float g_h1[NND * HID];
__device__ float g_agg[NND * HID];
__device__ int   g_cnt[NND];
__device__ int   g_rowstart[NND];
__device__ int   g_cursor[NND];
__device__ int   g_adj[NE];
__device__ int   g_blocksum[CSR_BLOCKS];
__device__ int   g_bar_count;
__device__ int   g_bar_sense;

typedef unsigned long long ull;
union U2 { ull u; float2 f; };

__device__ __forceinline__ ull pack2(float v) {
    ull r; asm("mov.b64 %0, {%1, %1};" : "=l"(r) : "f"(v)); return r;
}
__device__ __forceinline__ ull packf2(float lo, float hi) {
    ull r; asm("mov.b64 %0, {%1, %2};" : "=l"(r) : "f"(lo), "f"(hi)); return r;
}
__device__ __forceinline__ void fma2(ull& d, ull a, ull b) {
    asm("fma.rn.f32x2 %0, %1, %2, %0;" : "+l"(d) : "l"(a), "l"(b));
}
__device__ __forceinline__ float2 unpk(ull v) {
    float2 r; asm("mov.b64 {%0, %1}, %2;" : "=f"(r.x), "=f"(r.y) : "l"(v)); return r;
}
__device__ __forceinline__ float prelu(float v, float a) { return v >= 0.f ? v : a * v; }

// ---------------- launch 1: zero cnt + reset barrier + embedding gather -----
__global__ void prep_kernel(const int* __restrict__ x,
                            const float* __restrict__ emb,
                            float* __restrict__ h0) {
    int t = blockIdx.x * blockDim.x + threadIdx.x;
    if (t < NND) g_cnt[t] = 0;
    if (t == 0) { g_bar_count = 0; g_bar_sense = 0; }
    int i = t >> 4;
    int p = (t & 15) << 2;
    int xi = __ldg(&x[i]);
    *(float4*)&h0[i * HID + p] = *(const float4*)&emb[xi * HID + p];
}

// ---------------- software grid barrier -------------------------------------
__device__ __forceinline__ void grid_barrier(int phase) {
    __threadfence();
    __syncthreads();
    if (threadIdx.x == 0) {
        int v = atomicAdd(&g_bar_count, 1);
        if (v == CSR_BLOCKS - 1) {
            atomicExch(&g_bar_count, 0);
            __threadfence();
            atomicExch(&g_bar_sense, phase);
        } else {
            while (true) {
                int s;
                asm volatile("ld.global.cg.s32 %0, [%1];" : "=r"(s) : "l"(&g_bar_sense));
                if (s >= phase) break;
                __nanosleep(64);
            }
        }
    }
    __syncthreads();
}

// ---------------- launch 2: persistent CSR build ----------------------------
__global__ __launch_bounds__(CSR_THREADS) void csr_kernel(const int* __restrict__ ei) {
    const int tid = threadIdx.x, bid = blockIdx.x;
    const int gid = bid * CSR_THREADS + tid;
    const int gstride = CSR_BLOCKS * CSR_THREADS;

    for (int e = gid; e < NE; e += gstride)
        atomicAdd(&g_cnt[__ldg(&ei[NE + e])], 1);
    grid_barrier(1);

    __shared__ int swarp[32];
    __shared__ int soff[CSR_BLOCKS];
    int v = 0;
    if (gid < NND)
        asm volatile("ld.global.cg.s32 %0, [%1];" : "=r"(v) : "l"(&g_cnt[gid]));
    const int lane = tid & 31, wid = tid >> 5;
    int x = v;
    #pragma unroll
    for (int d = 1; d < 32; d <<= 1) { int t = __shfl_up_sync(~0u, x, d); if (lane >= d) x += t; }
    if (lane == 31) swarp[wid] = x;
    __syncthreads();
    if (wid == 0) {
        int y = swarp[lane];
        int z = y;
        #pragma unroll
        for (int d = 1; d < 32; d <<= 1) { int t = __shfl_up_sync(~0u, z, d); if (lane >= d) z += t; }
        swarp[lane] = z - y;
    }
    __syncthreads();
    const int excl = x - v + swarp[wid];
    if (tid == CSR_THREADS - 1) g_blocksum[bid] = excl + v;
    grid_barrier(2);

    if (tid < CSR_BLOCKS) {
        int b;
        asm volatile("ld.global.cg.s32 %0, [%1];" : "=r"(b) : "l"(&g_blocksum[tid]));
        soff[tid] = b;
    }
    __syncthreads();
    if (tid == 0) {
        int run = 0;
        for (int i = 0; i < CSR_BLOCKS; i++) { int t = soff[i]; soff[i] = run; run += t; }
    }
    __syncthreads();
    if (gid < NND) {
        int st = excl + soff[bid];
        g_rowstart[gid] = st;
        g_cursor[gid] = st;
    }
    grid_barrier(3);

    for (int e = gid; e < NE; e += gstride) {
        int src = __ldg(&ei[e]);
        int dst = __ldg(&ei[NE + e]);
        int pp = atomicAdd(&g_cursor[dst], 1);
        g_adj[pp] = src;
    }
}

// ---------------- mean aggregation (lean, high-occupancy) -------------------
__global__ __launch_bounds__(256) void agg_kernel(const float* __restrict__ h,
                                                  float* __restrict__ aggout) {
    const int tid = threadIdx.x;
    const int gid = blockIdx.x * 256 + tid;
    const int node = gid >> 4;
    if (node >= NND) return;
    const int lane16 = tid & 15;
    const int p4 = lane16 << 2;
    const unsigned smask = 0xFFFFu << (tid & 16);

    const int st = __ldg(&g_rowstart[node]);
    const int n  = __ldg(&g_cnt[node]);
    float4 acc = make_float4(0.f, 0.f, 0.f, 0.f);
    for (int j = 0; j < n; j += 16) {
        const int m = min(16, n - j);
        int idx = 0;
        if (lane16 < m) idx = __ldg(&g_adj[st + j + lane16]);
        int jj = 0;
        for (; jj + 4 <= m; jj += 4) {
            int s0 = __shfl_sync(smask, idx, jj + 0, 16);
            int s1 = __shfl_sync(smask, idx, jj + 1, 16);
            int s2 = __shfl_sync(smask, idx, jj + 2, 16);
            int s3 = __shfl_sync(smask, idx, jj + 3, 16);
            float4 v0 = *(const float4*)&h[s0 * HID + p4];
            float4 v1 = *(const float4*)&h[s1 * HID + p4];
            float4 v2 = *(const float4*)&h[s2 * HID + p4];
            float4 v3 = *(const float4*)&h[s3 * HID + p4];
            acc.x += (v0.x + v1.x) + (v2.x + v3.x);
            acc.y += (v0.y + v1.y) + (v2.y + v3.y);
            acc.z += (v0.z + v1.z) + (v2.z + v3.z);
            acc.w += (v0.w + v1.w) + (v2.w + v3.w);
        }
        for (; jj < m; jj++) {
            int s0 = __shfl_sync(smask, idx, jj, 16);
            float4 v0 = *(const float4*)&h[s0 * HID + p4];
            acc.x += v0.x; acc.y += v0.y; acc.z += v0.z; acc.w += v0.w;
        }
    }
    const float iv = 1.0f / (float)max(n, 1);
    *(float4*)&aggout[node * HID + p4] =
        make_float4(acc.x * iv, acc.y * iv, acc.z * iv, acc.w * iv);
}

// ---------------- dual GEMM as single K=128 GEMM (pair-packed) ---------------
// chunk = 128 nodes (64 pairs). warp = 8 pairs (16 rows) x 64 cols (2/lane).
// A packed: sAp[pair][k] = (a[2p][k], a[2p+1][k]) -> fma2 operand directly.
// W: LDS.64 per k, all 32 lanes distinct -> zero replication.
__global__ __launch_bounds__(256, 2) void gemm_dual_kernel(
    const float* __restrict__ h, const float* __restrict__ agg,
    const float* __restrict__ Wl, const float* __restrict__ bl,
    const float* __restrict__ Wr, const float* __restrict__ alpha_p,
    float* __restrict__ out)
{
    extern __shared__ float sm[];
    float* sW = sm;                                  // 128*64 floats
    float* sb = sW + 128 * 64;                       // 64
    ull*   sAp = (ull*)(sb + 64);                    // 64 pairs * APSTRIDE ulls

    const int tid = threadIdx.x;
    // stage stacked weights: rows 0..63 = Wl, 64..127 = Wr
    #pragma unroll
    for (int t = tid; t < 128 * 16; t += 256) {
        int k = t >> 4, q = (t & 15) << 2;
        float4 w = (k < 64) ? *(const float4*)&Wl[k * HID + q]
                            : *(const float4*)&Wr[(k - 64) * HID + q];
        *(float4*)&sW[k * 64 + q] = w;
    }
    if (tid < HID) sb[tid] = bl[tid];
    const float alpha = __ldg(alpha_p);

    const int lane = tid & 31;
    const int wid  = tid >> 5;
    const int pbase = wid << 3;                      // 8 pairs per warp
    const int c2 = lane << 1;
    const int nchunks = (NND + 127) / 128;           // 782

    for (int chunk = blockIdx.x; chunk < nchunks; chunk += gridDim.x) {
        const int base = chunk * 128;
        __syncthreads();
        // stage A pairs: task = (pair, 4-k group); K layout [mean(64) | h(64)]
        #pragma unroll
        for (int it = 0; it < 8; it++) {
            int idx = it * 256 + tid;
            int p  = idx >> 5;
            int kq = (idx & 31) << 2;
            int n0 = base + (p << 1), n1 = n0 + 1;
            float4 a0 = make_float4(0.f, 0.f, 0.f, 0.f);
            float4 a1 = make_float4(0.f, 0.f, 0.f, 0.f);
            if (kq < 64) {
                if (n0 < NND) a0 = *(const float4*)&agg[n0 * HID + kq];
                if (n1 < NND) a1 = *(const float4*)&agg[n1 * HID + kq];
            } else {
                if (n0 < NND) a0 = *(const float4*)&h[n0 * HID + kq - 64];
                if (n1 < NND) a1 = *(const float4*)&h[n1 * HID + kq - 64];
            }
            ull* dst = &sAp[p * APSTRIDE + kq];
            dst[0] = packf2(a0.x, a1.x);
            dst[1] = packf2(a0.y, a1.y);
            dst[2] = packf2(a0.z, a1.z);
            dst[3] = packf2(a0.w, a1.w);
        }
        __syncthreads();

        ull acc[8][2];
        {
            ull b0 = pack2(sb[c2]);
            ull b1 = pack2(sb[c2 + 1]);
            #pragma unroll
            for (int p = 0; p < 8; p++) { acc[p][0] = b0; acc[p][1] = b1; }
        }

        #pragma unroll 2
        for (int kb = 0; kb < 128; kb += 4) {
            ull wlo[4], whi[4];
            #pragma unroll
            for (int kk = 0; kk < 4; kk++) {
                float2 wv = *(const float2*)&sW[(kb + kk) * 64 + c2];
                wlo[kk] = pack2(wv.x);
                whi[kk] = pack2(wv.y);
            }
            #pragma unroll
            for (int p = 0; p < 8; p++) {
                const ull* ap = &sAp[(pbase + p) * APSTRIDE + kb];
                ulonglong2 A01 = *(const ulonglong2*)(ap);
                ulonglong2 A23 = *(const ulonglong2*)(ap + 2);
                fma2(acc[p][0], A01.x, wlo[0]); fma2(acc[p][1], A01.x, whi[0]);
                fma2(acc[p][0], A01.y, wlo[1]); fma2(acc[p][1], A01.y, whi[1]);
                fma2(acc[p][0], A23.x, wlo[2]); fma2(acc[p][1], A23.x, whi[2]);
                fma2(acc[p][0], A23.y, wlo[3]); fma2(acc[p][1], A23.y, whi[3]);
            }
        }

        #pragma unroll
        for (int p = 0; p < 8; p++) {
            int n0 = base + ((pbase + p) << 1), n1 = n0 + 1;
            float2 v0 = unpk(acc[p][0]);   // (n0_c0, n1_c0)
            float2 v1 = unpk(acc[p][1]);   // (n0_c1, n1_c1)
            if (n0 < NND)
                *(float2*)&out[n0 * HID + c2] =
                    make_float2(prelu(v0.x, alpha), prelu(v1.x, alpha));
            if (n1 < NND)
                *(float2*)&out[n1 * HID + c2] =
                    make_float2(prelu(v0.y, alpha), prelu(v1.y, alpha));
        }
    }
}

// ---------------- single GEMM (K=64): out = h @ W + b ------------------------
__global__ __launch_bounds__(256, 3) void gemm_single_kernel(
    const float* __restrict__ h,
    const float* __restrict__ W, const float* __restrict__ bb,
    float* __restrict__ out)
{
    extern __shared__ float sm[];
    float* sW = sm;                                  // 64*64
    float* sb = sW + 64 * 64;                        // 64
    ull*   sAp = (ull*)(sb + 64);                    // 64 pairs * APSTRIDE1

    const int tid = threadIdx.x;
    #pragma unroll
    for (int t = tid; t < 64 * 16; t += 256) {
        int k = t >> 4, q = (t & 15) << 2;
        *(float4*)&sW[k * 64 + q] = *(const float4*)&W[k * HID + q];
    }
    if (tid < HID) sb[tid] = bb[tid];

    const int lane = tid & 31;
    const int wid  = tid >> 5;
    const int pbase = wid << 3;
    const int c2 = lane << 1;
    const int nchunks = (NND + 127) / 128;

    for (int chunk = blockIdx.x; chunk < nchunks; chunk += gridDim.x) {
        const int base = chunk * 128;
        __syncthreads();
        #pragma unroll
        for (int it = 0; it < 4; it++) {
            int idx = it * 256 + tid;
            int p  = idx >> 4;
            int kq = (idx & 15) << 2;
            int n0 = base + (p << 1), n1 = n0 + 1;
            float4 a0 = make_float4(0.f, 0.f, 0.f, 0.f);
            float4 a1 = make_float4(0.f, 0.f, 0.f, 0.f);
            if (n0 < NND) a0 = *(const float4*)&h[n0 * HID + kq];
            if (n1 < NND) a1 = *(const float4*)&h[n1 * HID + kq];
            ull* dst = &sAp[p * APSTRIDE1 + kq];
            dst[0] = packf2(a0.x, a1.x);
            dst[1] = packf2(a0.y, a1.y);
            dst[2] = packf2(a0.z, a1.z);
            dst[3] = packf2(a0.w, a1.w);
        }
        __syncthreads();

        ull acc[8][2];
        {
            ull b0 = pack2(sb[c2]);
            ull b1 = pack2(sb[c2 + 1]);
            #pragma unroll
            for (int p = 0; p < 8; p++) { acc[p][0] = b0; acc[p][1] = b1; }
        }

        #pragma unroll 2
        for (int kb = 0; kb < 64; kb += 4) {
            ull wlo[4], whi[4];
            #pragma unroll
            for (int kk = 0; kk < 4; kk++) {
                float2 wv = *(const float2*)&sW[(kb + kk) * 64 + c2];
                wlo[kk] = pack2(wv.x);
                whi[kk] = pack2(wv.y);
            }
            #pragma unroll
            for (int p = 0; p < 8; p++) {
                const ull* ap = &sAp[(pbase + p) * APSTRIDE1 + kb];
                ulonglong2 A01 = *(const ulonglong2*)(ap);
                ulonglong2 A23 = *(const ulonglong2*)(ap + 2);
                fma2(acc[p][0], A01.x, wlo[0]); fma2(acc[p][1], A01.x, whi[0]);
                fma2(acc[p][0], A01.y, wlo[1]); fma2(acc[p][1], A01.y, whi[1]);
                fma2(acc[p][0], A23.x, wlo[2]); fma2(acc[p][1], A23.x, whi[2]);
                fma2(acc[p][0], A23.y, wlo[3]); fma2(acc[p][1], A23.y, whi[3]);
            }
        }

        #pragma unroll
        for (int p = 0; p < 8; p++) {
            int n0 = base + ((pbase + p) << 1), n1 = n0 + 1;
            float2 v0 = unpk(acc[p][0]);
            float2 v1 = unpk(acc[p][1]);
            if (n0 < NND) *(float2*)&out[n0 * HID + c2] = make_float2(v0.x, v1.x);
            if (n1 < NND) *(float2*)&out[n1 * HID + c2] = make_float2(v0.y, v1.y);
        }
    }
}

// ---------------- launch -----------------------------------------------------
extern "C" void kernel_launch(void* const* d_in, const int* in_sizes, int n_in,
                              void* d_out, int out_size) {
    const int*   x    = (const int*)d_in[0];
    const int*   ei   = (const int*)d_in[1];
    // d_in[2] = edge_weight : unused by the reference
    const float* emb  = (const float*)d_in[3];
    const float* Wl1  = (const float*)d_in[4];
    const float* bl1  = (const float*)d_in[5];
    const float* Wr1  = (const float*)d_in[6];
    const float* a1   = (const float*)d_in[7];
    const float* Wl2  = (const float*)d_in[8];
    const float* bl2  = (const float*)d_in[9];
    const float* Wr2  = (const float*)d_in[10];
    const float* a2   = (const float*)d_in[11];
    const float* Wout = (const float*)d_in[12];
    const float* bout = (const float*)d_in[13];
    float* out = (float*)d_out;

    float *h0, *h1, *agg;
    cudaGetSymbolAddress((void**)&h0,  g_h0);
    cudaGetSymbolAddress((void**)&h1,  g_h1);
    cudaGetSymbolAddress((void**)&agg, g_agg);

    const size_t smem_dual   = (128 * 64 + 64) * sizeof(float) + 64 * APSTRIDE  * sizeof(ull); // ~97KB
    const size_t smem_single = (64 * 64 + 64)  * sizeof(float) + 64 * APSTRIDE1 * sizeof(ull); // ~50KB
    cudaFuncSetAttribute(gemm_dual_kernel,
                         cudaFuncAttributeMaxDynamicSharedMemorySize, (int)smem_dual);
    cudaFuncSetAttribute(gemm_single_kernel,
                         cudaFuncAttributeMaxDynamicSharedMemorySize, (int)smem_single);

    const int g_agg_grid = (NND * 16) / 256;   // 6250

    prep_kernel<<<g_agg_grid, 256>>>(x, emb, h0);
    csr_kernel<<<CSR_BLOCKS, CSR_THREADS>>>(ei);

    // layer 1
    agg_kernel<<<g_agg_grid, 256>>>(h0, agg);
    gemm_dual_kernel<<<296, 256, smem_dual>>>(h0, agg, Wl1, bl1, Wr1, a1, h1);

    // layer 2
    agg_kernel<<<g_agg_grid, 256>>>(h1, agg);
    gemm_dual_kernel<<<296, 256, smem_dual>>>(h1, agg, Wl2, bl2, Wr2, a2, h0);

    // output projection
    gemm_single_kernel<<<444, 256, smem_single>>>(h0, Wout, bout, out);
}

// round 7
// speedup vs baseline: 1.7890x; 1.0528x over previous
#include <cuda_runtime.h>

#define NND 100000
#define NE  1250000
#define HID 64
#define CSR_BLOCKS 98
#define CSR_THREADS 1024

#define APSTRIDE 130   // sAp pair stride in ulls (K=128 + pad)
#define APSTRIDE1 66   // sAp pair stride for K=64

// ---------------- scratch (device globals; no allocation allowed) ----------
__device__ float g_h0[NND * HID];
__device__ float g_h1[NND * HID];
__device__ float g_agg[NND * HID];
__device__ int   g_cnt[NND];
__device__ int   g_rowstart[NND];
__device__ int   g_cursor[NND];
__device__ int   g_adj[NE];
__device__ int   g_blocksum[CSR_BLOCKS];
__device__ int   g_bar_count;
__device__ int   g_bar_sense;

typedef unsigned long long ull;

__device__ __forceinline__ ull pack2(float v) {
    ull r; asm("mov.b64 %0, {%1, %1};" : "=l"(r) : "f"(v)); return r;
}
__device__ __forceinline__ ull packf2(float lo, float hi) {
    ull r; asm("mov.b64 %0, {%1, %2};" : "=l"(r) : "f"(lo), "f"(hi)); return r;
}
__device__ __forceinline__ void fma2(ull& d, ull a, ull b) {
    asm("fma.rn.f32x2 %0, %1, %2, %0;" : "+l"(d) : "l"(a), "l"(b));
}
__device__ __forceinline__ float2 unpk(ull v) {
    float2 r; asm("mov.b64 {%0, %1}, %2;" : "=f"(r.x), "=f"(r.y) : "l"(v)); return r;
}
__device__ __forceinline__ float prelu(float v, float a) { return v >= 0.f ? v : a * v; }

// ---------------- launch 1: zero cnt + reset barrier + embedding gather -----
__global__ void prep_kernel(const int* __restrict__ x,
                            const float* __restrict__ emb,
                            float* __restrict__ h0) {
    int t = blockIdx.x * blockDim.x + threadIdx.x;
    if (t < NND) g_cnt[t] = 0;
    if (t == 0) { g_bar_count = 0; g_bar_sense = 0; }
    int i = t >> 4;
    int p = (t & 15) << 2;
    int xi = __ldg(&x[i]);
    *(float4*)&h0[i * HID + p] = *(const float4*)&emb[xi * HID + p];
}

// ---------------- software grid barrier -------------------------------------
__device__ __forceinline__ void grid_barrier(int phase) {
    __threadfence();
    __syncthreads();
    if (threadIdx.x == 0) {
        int v = atomicAdd(&g_bar_count, 1);
        if (v == CSR_BLOCKS - 1) {
            atomicExch(&g_bar_count, 0);
            __threadfence();
            atomicExch(&g_bar_sense, phase);
        } else {
            while (true) {
                int s;
                asm volatile("ld.global.cg.s32 %0, [%1];" : "=r"(s) : "l"(&g_bar_sense));
                if (s >= phase) break;
                __nanosleep(64);
            }
        }
    }
    __syncthreads();
}

// ---------------- launch 2: persistent CSR build ----------------------------
__global__ __launch_bounds__(CSR_THREADS) void csr_kernel(const int* __restrict__ ei) {
    const int tid = threadIdx.x, bid = blockIdx.x;
    const int gid = bid * CSR_THREADS + tid;
    const int gstride = CSR_BLOCKS * CSR_THREADS;

    for (int e = gid; e < NE; e += gstride)
        atomicAdd(&g_cnt[__ldg(&ei[NE + e])], 1);
    grid_barrier(1);

    __shared__ int swarp[32];
    __shared__ int soff[CSR_BLOCKS];
    int v = 0;
    if (gid < NND)
        asm volatile("ld.global.cg.s32 %0, [%1];" : "=r"(v) : "l"(&g_cnt[gid]));
    const int lane = tid & 31, wid = tid >> 5;
    int x = v;
    #pragma unroll
    for (int d = 1; d < 32; d <<= 1) { int t = __shfl_up_sync(~0u, x, d); if (lane >= d) x += t; }
    if (lane == 31) swarp[wid] = x;
    __syncthreads();
    if (wid == 0) {
        int y = swarp[lane];
        int z = y;
        #pragma unroll
        for (int d = 1; d < 32; d <<= 1) { int t = __shfl_up_sync(~0u, z, d); if (lane >= d) z += t; }
        swarp[lane] = z - y;
    }
    __syncthreads();
    const int excl = x - v + swarp[wid];
    if (tid == CSR_THREADS - 1) g_blocksum[bid] = excl + v;
    grid_barrier(2);

    if (tid < CSR_BLOCKS) {
        int b;
        asm volatile("ld.global.cg.s32 %0, [%1];" : "=r"(b) : "l"(&g_blocksum[tid]));
        soff[tid] = b;
    }
    __syncthreads();
    if (tid == 0) {
        int run = 0;
        for (int i = 0; i < CSR_BLOCKS; i++) { int t = soff[i]; soff[i] = run; run += t; }
    }
    __syncthreads();
    if (gid < NND) {
        int st = excl + soff[bid];
        g_rowstart[gid] = st;
        g_cursor[gid] = st;
    }
    grid_barrier(3);

    for (int e = gid; e < NE; e += gstride) {
        int src = __ldg(&ei[e]);
        int dst = __ldg(&ei[NE + e]);
        int pp = atomicAdd(&g_cursor[dst], 1);
        g_adj[pp] = src;
    }
}

// ---------------- mean aggregation (lean, high-occupancy) -------------------
__global__ __launch_bounds__(256) void agg_kernel(const float* __restrict__ h,
                                                  float* __restrict__ aggout) {
    const int tid = threadIdx.x;
    const int gid = blockIdx.x * 256 + tid;
    const int node = gid >> 4;
    if (node >= NND) return;
    const int lane16 = tid & 15;
    const int p4 = lane16 << 2;
    const unsigned smask = 0xFFFFu << (tid & 16);

    const int st = __ldg(&g_rowstart[node]);
    const int n  = __ldg(&g_cnt[node]);
    float4 acc = make_float4(0.f, 0.f, 0.f, 0.f);
    for (int j = 0; j < n; j += 16) {
        const int m = min(16, n - j);
        int idx = 0;
        if (lane16 < m) idx = __ldg(&g_adj[st + j + lane16]);
        int jj = 0;
        for (; jj + 4 <= m; jj += 4) {
            int s0 = __shfl_sync(smask, idx, jj + 0, 16);
            int s1 = __shfl_sync(smask, idx, jj + 1, 16);
            int s2 = __shfl_sync(smask, idx, jj + 2, 16);
            int s3 = __shfl_sync(smask, idx, jj + 3, 16);
            float4 v0 = *(const float4*)&h[s0 * HID + p4];
            float4 v1 = *(const float4*)&h[s1 * HID + p4];
            float4 v2 = *(const float4*)&h[s2 * HID + p4];
            float4 v3 = *(const float4*)&h[s3 * HID + p4];
            acc.x += (v0.x + v1.x) + (v2.x + v3.x);
            acc.y += (v0.y + v1.y) + (v2.y + v3.y);
            acc.z += (v0.z + v1.z) + (v2.z + v3.z);
            acc.w += (v0.w + v1.w) + (v2.w + v3.w);
        }
        for (; jj < m; jj++) {
            int s0 = __shfl_sync(smask, idx, jj, 16);
            float4 v0 = *(const float4*)&h[s0 * HID + p4];
            acc.x += v0.x; acc.y += v0.y; acc.z += v0.z; acc.w += v0.w;
        }
    }
    const float iv = 1.0f / (float)max(n, 1);
    *(float4*)&aggout[node * HID + p4] =
        make_float4(acc.x * iv, acc.y * iv, acc.z * iv, acc.w * iv);
}

// ---------------- dual GEMM as single K=128 GEMM (half-warp split) ----------
// chunk = 128 nodes = 64 pairs. warp = 2 halves x 16 lanes.
// Each half: 4 pairs x 64 cols (4 cols/lane). Each A broadcast feeds 4 accs.
__global__ __launch_bounds__(256, 2) void gemm_dual_kernel(
    const float* __restrict__ h, const float* __restrict__ agg,
    const float* __restrict__ Wl, const float* __restrict__ bl,
    const float* __restrict__ Wr, const float* __restrict__ alpha_p,
    float* __restrict__ out)
{
    extern __shared__ float sm[];
    float* sW = sm;                                  // 128*64 floats
    float* sb = sW + 128 * 64;                       // 64
    ull*   sAp = (ull*)(sb + 64);                    // 64 pairs * APSTRIDE ulls

    const int tid = threadIdx.x;
    // stage stacked weights: rows 0..63 = Wl, 64..127 = Wr
    #pragma unroll
    for (int t = tid; t < 128 * 16; t += 256) {
        int k = t >> 4, q = (t & 15) << 2;
        float4 w = (k < 64) ? *(const float4*)&Wl[k * HID + q]
                            : *(const float4*)&Wr[(k - 64) * HID + q];
        *(float4*)&sW[k * 64 + q] = w;
    }
    if (tid < HID) sb[tid] = bl[tid];
    const float alpha = __ldg(alpha_p);

    const int lane  = tid & 31;
    const int wid   = tid >> 5;
    const int half  = lane >> 4;
    const int lane16 = lane & 15;
    const int pbase = (wid << 3) + (half << 2);      // 4 pairs per half
    const int c4 = lane16 << 2;                      // 4 cols per lane
    const int nchunks = (NND + 127) / 128;           // 782

    for (int chunk = blockIdx.x; chunk < nchunks; chunk += gridDim.x) {
        const int base = chunk * 128;
        __syncthreads();
        // stage A pairs: sAp[p][k] = (a[2p][k], a[2p+1][k]); K = [mean | h]
        #pragma unroll
        for (int it = 0; it < 8; it++) {
            int idx = it * 256 + tid;
            int p  = idx >> 5;
            int kq = (idx & 31) << 2;
            int n0 = base + (p << 1), n1 = n0 + 1;
            float4 a0 = make_float4(0.f, 0.f, 0.f, 0.f);
            float4 a1 = make_float4(0.f, 0.f, 0.f, 0.f);
            if (kq < 64) {
                if (n0 < NND) a0 = *(const float4*)&agg[n0 * HID + kq];
                if (n1 < NND) a1 = *(const float4*)&agg[n1 * HID + kq];
            } else {
                if (n0 < NND) a0 = *(const float4*)&h[n0 * HID + kq - 64];
                if (n1 < NND) a1 = *(const float4*)&h[n1 * HID + kq - 64];
            }
            ull* dst = &sAp[p * APSTRIDE + kq];
            dst[0] = packf2(a0.x, a1.x);
            dst[1] = packf2(a0.y, a1.y);
            dst[2] = packf2(a0.z, a1.z);
            dst[3] = packf2(a0.w, a1.w);
        }
        __syncthreads();

        ull acc[4][4];   // [pair][col]
        {
            float4 bv = *(const float4*)&sb[c4];
            #pragma unroll
            for (int i = 0; i < 4; i++) {
                acc[i][0] = pack2(bv.x); acc[i][1] = pack2(bv.y);
                acc[i][2] = pack2(bv.z); acc[i][3] = pack2(bv.w);
            }
        }

        #pragma unroll 4
        for (int kb = 0; kb < 128; kb += 2) {
            // W: 2 ks x 4 cols
            float4 w0 = *(const float4*)&sW[kb * 64 + c4];
            float4 w1 = *(const float4*)&sW[(kb + 1) * 64 + c4];
            ull wp0[4] = { pack2(w0.x), pack2(w0.y), pack2(w0.z), pack2(w0.w) };
            ull wp1[4] = { pack2(w1.x), pack2(w1.y), pack2(w1.z), pack2(w1.w) };
            // A: 4 pairs x 2 ks
            ulonglong2 A[4];
            #pragma unroll
            for (int i = 0; i < 4; i++)
                A[i] = *(const ulonglong2*)&sAp[(pbase + i) * APSTRIDE + kb];
            #pragma unroll
            for (int i = 0; i < 4; i++) {
                fma2(acc[i][0], A[i].x, wp0[0]); fma2(acc[i][1], A[i].x, wp0[1]);
                fma2(acc[i][2], A[i].x, wp0[2]); fma2(acc[i][3], A[i].x, wp0[3]);
                fma2(acc[i][0], A[i].y, wp1[0]); fma2(acc[i][1], A[i].y, wp1[1]);
                fma2(acc[i][2], A[i].y, wp1[2]); fma2(acc[i][3], A[i].y, wp1[3]);
            }
        }

        #pragma unroll
        for (int i = 0; i < 4; i++) {
            int n0 = base + ((pbase + i) << 1), n1 = n0 + 1;
            float2 v0 = unpk(acc[i][0]), v1 = unpk(acc[i][1]);
            float2 v2 = unpk(acc[i][2]), v3 = unpk(acc[i][3]);
            if (n0 < NND)
                *(float4*)&out[n0 * HID + c4] =
                    make_float4(prelu(v0.x, alpha), prelu(v1.x, alpha),
                                prelu(v2.x, alpha), prelu(v3.x, alpha));
            if (n1 < NND)
                *(float4*)&out[n1 * HID + c4] =
                    make_float4(prelu(v0.y, alpha), prelu(v1.y, alpha),
                                prelu(v2.y, alpha), prelu(v3.y, alpha));
        }
    }
}

// ---------------- single GEMM (K=64), half-warp split ------------------------
__global__ __launch_bounds__(256, 3) void gemm_single_kernel(
    const float* __restrict__ h,
    const float* __restrict__ W, const float* __restrict__ bb,
    float* __restrict__ out)
{
    extern __shared__ float sm[];
    float* sW = sm;                                  // 64*64
    float* sb = sW + 64 * 64;                        // 64
    ull*   sAp = (ull*)(sb + 64);                    // 64 pairs * APSTRIDE1

    const int tid = threadIdx.x;
    #pragma unroll
    for (int t = tid; t < 64 * 16; t += 256) {
        int k = t >> 4, q = (t & 15) << 2;
        *(float4*)&sW[k * 64 + q] = *(const float4*)&W[k * HID + q];
    }
    if (tid < HID) sb[tid] = bb[tid];

    const int lane  = tid & 31;
    const int wid   = tid >> 5;
    const int half  = lane >> 4;
    const int lane16 = lane & 15;
    const int pbase = (wid << 3) + (half << 2);
    const int c4 = lane16 << 2;
    const int nchunks = (NND + 127) / 128;

    for (int chunk = blockIdx.x; chunk < nchunks; chunk += gridDim.x) {
        const int base = chunk * 128;
        __syncthreads();
        #pragma unroll
        for (int it = 0; it < 4; it++) {
            int idx = it * 256 + tid;
            int p  = idx >> 4;
            int kq = (idx & 15) << 2;
            int n0 = base + (p << 1), n1 = n0 + 1;
            float4 a0 = make_float4(0.f, 0.f, 0.f, 0.f);
            float4 a1 = make_float4(0.f, 0.f, 0.f, 0.f);
            if (n0 < NND) a0 = *(const float4*)&h[n0 * HID + kq];
            if (n1 < NND) a1 = *(const float4*)&h[n1 * HID + kq];
            ull* dst = &sAp[p * APSTRIDE1 + kq];
            dst[0] = packf2(a0.x, a1.x);
            dst[1] = packf2(a0.y, a1.y);
            dst[2] = packf2(a0.z, a1.z);
            dst[3] = packf2(a0.w, a1.w);
        }
        __syncthreads();

        ull acc[4][4];
        {
            float4 bv = *(const float4*)&sb[c4];
            #pragma unroll
            for (int i = 0; i < 4; i++) {
                acc[i][0] = pack2(bv.x); acc[i][1] = pack2(bv.y);
                acc[i][2] = pack2(bv.z); acc[i][3] = pack2(bv.w);
            }
        }

        #pragma unroll 4
        for (int kb = 0; kb < 64; kb += 2) {
            float4 w0 = *(const float4*)&sW[kb * 64 + c4];
            float4 w1 = *(const float4*)&sW[(kb + 1) * 64 + c4];
            ull wp0[4] = { pack2(w0.x), pack2(w0.y), pack2(w0.z), pack2(w0.w) };
            ull wp1[4] = { pack2(w1.x), pack2(w1.y), pack2(w1.z), pack2(w1.w) };
            ulonglong2 A[4];
            #pragma unroll
            for (int i = 0; i < 4; i++)
                A[i] = *(const ulonglong2*)&sAp[(pbase + i) * APSTRIDE1 + kb];
            #pragma unroll
            for (int i = 0; i < 4; i++) {
                fma2(acc[i][0], A[i].x, wp0[0]); fma2(acc[i][1], A[i].x, wp0[1]);
                fma2(acc[i][2], A[i].x, wp0[2]); fma2(acc[i][3], A[i].x, wp0[3]);
                fma2(acc[i][0], A[i].y, wp1[0]); fma2(acc[i][1], A[i].y, wp1[1]);
                fma2(acc[i][2], A[i].y, wp1[2]); fma2(acc[i][3], A[i].y, wp1[3]);
            }
        }

        #pragma unroll
        for (int i = 0; i < 4; i++) {
            int n0 = base + ((pbase + i) << 1), n1 = n0 + 1;
            float2 v0 = unpk(acc[i][0]), v1 = unpk(acc[i][1]);
            float2 v2 = unpk(acc[i][2]), v3 = unpk(acc[i][3]);
            if (n0 < NND)
                *(float4*)&out[n0 * HID + c4] = make_float4(v0.x, v1.x, v2.x, v3.x);
            if (n1 < NND)
                *(float4*)&out[n1 * HID + c4] = make_float4(v0.y, v1.y, v2.y, v3.y);
        }
    }
}

// ---------------- launch -----------------------------------------------------
extern "C" void kernel_launch(void* const* d_in, const int* in_sizes, int n_in,
                              void* d_out, int out_size) {
    const int*   x    = (const int*)d_in[0];
    const int*   ei   = (const int*)d_in[1];
    // d_in[2] = edge_weight : unused by the reference
    const float* emb  = (const float*)d_in[3];
    const float* Wl1  = (const float*)d_in[4];
    const float* bl1  = (const float*)d_in[5];
    const float* Wr1  = (const float*)d_in[6];
    const float* a1   = (const float*)d_in[7];
    const float* Wl2  = (const float*)d_in[8];
    const float* bl2  = (const float*)d_in[9];
    const float* Wr2  = (const float*)d_in[10];
    const float* a2   = (const float*)d_in[11];
    const float* Wout = (const float*)d_in[12];
    const float* bout = (const float*)d_in[13];
    float* out = (float*)d_out;

    float *h0, *h1, *agg;
    cudaGetSymbolAddress((void**)&h0,  g_h0);
    cudaGetSymbolAddress((void**)&h1,  g_h1);
    cudaGetSymbolAddress((void**)&agg, g_agg);

    const size_t smem_dual   = (128 * 64 + 64) * sizeof(float) + 64 * APSTRIDE  * sizeof(ull); // ~97KB
    const size_t smem_single = (64 * 64 + 64)  * sizeof(float) + 64 * APSTRIDE1 * sizeof(ull); // ~50KB
    cudaFuncSetAttribute(gemm_dual_kernel,
                         cudaFuncAttributeMaxDynamicSharedMemorySize, (int)smem_dual);
    cudaFuncSetAttribute(gemm_single_kernel,
                         cudaFuncAttributeMaxDynamicSharedMemorySize, (int)smem_single);

    const int g_agg_grid = (NND * 16) / 256;   // 6250

    prep_kernel<<<g_agg_grid, 256>>>(x, emb, h0);
    csr_kernel<<<CSR_BLOCKS, CSR_THREADS>>>(ei);

    // layer 1
    agg_kernel<<<g_agg_grid, 256>>>(h0, agg);
    gemm_dual_kernel<<<296, 256, smem_dual>>>(h0, agg, Wl1, bl1, Wr1, a1, h1);

    // layer 2
    agg_kernel<<<g_agg_grid, 256>>>(h1, agg);
    gemm_dual_kernel<<<296, 256, smem_dual>>>(h1, agg, Wl2, bl2, Wr2, a2, h0);

    // output projection
    gemm_single_kernel<<<444, 256, smem_single>>>(h0, Wout, bout, out);
}

// round 9
// speedup vs baseline: 1.8602x; 1.0398x over previous
#include <cuda_runtime.h>

#define NND 100000
#define NE  1250000
#define HID 64
#define CSR_BLOCKS 98
#define CSR_THREADS 1024

#define APSTRIDE1 66   // sAp pair stride in ulls (K=64 + pad)

// ---------------- scratch (device globals; no allocation allowed) ----------
__device__ float g_h0[NND * HID];
__device__ float g_h1[NND * HID];
__device__ float g_agg[NND * HID];
__device__ int   g_cnt[NND];
__device__ int   g_rowstart[NND];
__device__ int   g_cursor[NND];
__device__ int   g_adj[NE];
__device__ int   g_blocksum[CSR_BLOCKS];
__device__ int   g_bar_count;
__device__ int   g_bar_sense;

typedef unsigned long long ull;

__device__ __forceinline__ ull pack2(float v) {
    ull r; asm("mov.b64 %0, {%1, %1};" : "=l"(r) : "f"(v)); return r;
}
__device__ __forceinline__ ull packf2(float lo, float hi) {
    ull r; asm("mov.b64 %0, {%1, %2};" : "=l"(r) : "f"(lo), "f"(hi)); return r;
}
__device__ __forceinline__ void fma2(ull& d, ull a, ull b) {
    asm("fma.rn.f32x2 %0, %1, %2, %0;" : "+l"(d) : "l"(a), "l"(b));
}
__device__ __forceinline__ float2 unpk(ull v) {
    float2 r; asm("mov.b64 {%0, %1}, %2;" : "=f"(r.x), "=f"(r.y) : "l"(v)); return r;
}
__device__ __forceinline__ float prelu(float v, float a) { return v >= 0.f ? v : a * v; }

// ---------------- launch 1: gather + zero cnt --------------------------------
__global__ void prep_kernel(const int* __restrict__ x,
                            const float* __restrict__ emb,
                            float* __restrict__ h0) {
    int t = blockIdx.x * blockDim.x + threadIdx.x;
    if (t < NND) g_cnt[t] = 0;
    if (t == 0) { g_bar_count = 0; g_bar_sense = 0; }
    int i = t >> 4;
    int p = (t & 15) << 2;
    int xi = __ldg(&x[i]);
    *(float4*)&h0[i * HID + p] = *(const float4*)&emb[xi * HID + p];
}

// ---------------- launch 2: degree count -------------------------------------
__global__ void count_kernel(const int* __restrict__ ei) {
    int e = blockIdx.x * blockDim.x + threadIdx.x;
    if (e < NE) atomicAdd(&g_cnt[__ldg(&ei[NE + e])], 1);
}

// ---------------- software grid barrier -------------------------------------
__device__ __forceinline__ void grid_barrier(int phase) {
    __threadfence();
    __syncthreads();
    if (threadIdx.x == 0) {
        int v = atomicAdd(&g_bar_count, 1);
        if (v == CSR_BLOCKS - 1) {
            atomicExch(&g_bar_count, 0);
            __threadfence();
            atomicExch(&g_bar_sense, phase);
        } else {
            while (true) {
                int s;
                asm volatile("ld.global.cg.s32 %0, [%1];" : "=r"(s) : "l"(&g_bar_sense));
                if (s >= phase) break;
                __nanosleep(64);
            }
        }
    }
    __syncthreads();
}

// ---------------- launch 3: persistent CSR scan + fill ----------------------
__global__ __launch_bounds__(CSR_THREADS) void csr_kernel(const int* __restrict__ ei) {
    const int tid = threadIdx.x, bid = blockIdx.x;
    const int gid = bid * CSR_THREADS + tid;
    const int gstride = CSR_BLOCKS * CSR_THREADS;

    __shared__ int swarp[32];
    __shared__ int soff[CSR_BLOCKS];
    int v = 0;
    if (gid < NND) v = g_cnt[gid];
    const int lane = tid & 31, wid = tid >> 5;
    int x = v;
    #pragma unroll
    for (int d = 1; d < 32; d <<= 1) { int t = __shfl_up_sync(~0u, x, d); if (lane >= d) x += t; }
    if (lane == 31) swarp[wid] = x;
    __syncthreads();
    if (wid == 0) {
        int y = swarp[lane];
        int z = y;
        #pragma unroll
        for (int d = 1; d < 32; d <<= 1) { int t = __shfl_up_sync(~0u, z, d); if (lane >= d) z += t; }
        swarp[lane] = z - y;
    }
    __syncthreads();
    const int excl = x - v + swarp[wid];
    if (tid == CSR_THREADS - 1) g_blocksum[bid] = excl + v;
    grid_barrier(1);

    if (tid < CSR_BLOCKS) {
        int b;
        asm volatile("ld.global.cg.s32 %0, [%1];" : "=r"(b) : "l"(&g_blocksum[tid]));
        soff[tid] = b;
    }
    __syncthreads();
    if (tid == 0) {
        int run = 0;
        for (int i = 0; i < CSR_BLOCKS; i++) { int t = soff[i]; soff[i] = run; run += t; }
    }
    __syncthreads();
    if (gid < NND) {
        int st = excl + soff[bid];
        g_rowstart[gid] = st;
        g_cursor[gid] = st;
    }
    grid_barrier(2);

    for (int e = gid; e < NE; e += gstride) {
        int src = __ldg(&ei[e]);
        int dst = __ldg(&ei[NE + e]);
        int pp = atomicAdd(&g_cursor[dst], 1);
        g_adj[pp] = src;
    }
}

// ---------------- mean aggregation (lean, high-occupancy) -------------------
__global__ __launch_bounds__(256) void agg_kernel(const float* __restrict__ h,
                                                  float* __restrict__ aggout) {
    const int tid = threadIdx.x;
    const int gid = blockIdx.x * 256 + tid;
    const int node = gid >> 4;
    if (node >= NND) return;
    const int lane16 = tid & 15;
    const int p4 = lane16 << 2;
    const unsigned smask = 0xFFFFu << (tid & 16);

    const int st = __ldg(&g_rowstart[node]);
    const int n  = __ldg(&g_cnt[node]);
    float4 acc = make_float4(0.f, 0.f, 0.f, 0.f);
    for (int j = 0; j < n; j += 16) {
        const int m = min(16, n - j);
        int idx = 0;
        if (lane16 < m) idx = __ldg(&g_adj[st + j + lane16]);
        int jj = 0;
        for (; jj + 4 <= m; jj += 4) {
            int s0 = __shfl_sync(smask, idx, jj + 0, 16);
            int s1 = __shfl_sync(smask, idx, jj + 1, 16);
            int s2 = __shfl_sync(smask, idx, jj + 2, 16);
            int s3 = __shfl_sync(smask, idx, jj + 3, 16);
            float4 v0 = *(const float4*)&h[s0 * HID + p4];
            float4 v1 = *(const float4*)&h[s1 * HID + p4];
            float4 v2 = *(const float4*)&h[s2 * HID + p4];
            float4 v3 = *(const float4*)&h[s3 * HID + p4];
            acc.x += (v0.x + v1.x) + (v2.x + v3.x);
            acc.y += (v0.y + v1.y) + (v2.y + v3.y);
            acc.z += (v0.z + v1.z) + (v2.z + v3.z);
            acc.w += (v0.w + v1.w) + (v2.w + v3.w);
        }
        for (; jj < m; jj++) {
            int s0 = __shfl_sync(smask, idx, jj, 16);
            float4 v0 = *(const float4*)&h[s0 * HID + p4];
            acc.x += v0.x; acc.y += v0.y; acc.z += v0.z; acc.w += v0.w;
        }
    }
    const float iv = 1.0f / (float)max(n, 1);
    *(float4*)&aggout[node * HID + p4] =
        make_float4(acc.x * iv, acc.y * iv, acc.z * iv, acc.w * iv);
}

// ---------------- dual GEMM, K split into 2 phases (mean, h) ----------------
// chunk = 128 nodes = 64 pairs. A buffer holds 64 ks -> ~67KB total -> 3 CTAs/SM.
// warp = 2 halves x 16 lanes; half = 4 pairs x 64 cols (4 cols/lane).
__global__ __launch_bounds__(256, 3) void gemm_dual_kernel(
    const float* __restrict__ h, const float* __restrict__ agg,
    const float* __restrict__ Wl, const float* __restrict__ bl,
    const float* __restrict__ Wr, const float* __restrict__ alpha_p,
    float* __restrict__ out)
{
    extern __shared__ float sm[];
    float* sW = sm;                                  // 128*64 floats (Wl ; Wr)
    float* sb = sW + 128 * 64;                       // 64
    ull*   sAp = (ull*)(sb + 64);                    // 64 pairs * APSTRIDE1 ulls

    const int tid = threadIdx.x;
    #pragma unroll
    for (int t = tid; t < 128 * 16; t += 256) {
        int k = t >> 4, q = (t & 15) << 2;
        float4 w = (k < 64) ? *(const float4*)&Wl[k * HID + q]
                            : *(const float4*)&Wr[(k - 64) * HID + q];
        *(float4*)&sW[k * 64 + q] = w;
    }
    if (tid < HID) sb[tid] = bl[tid];
    const float alpha = __ldg(alpha_p);
    __syncthreads();    // sb/sW visible to ALL threads before acc init (R8 bug fix)

    const int lane  = tid & 31;
    const int wid   = tid >> 5;
    const int half  = lane >> 4;
    const int lane16 = lane & 15;
    const int pbase = (wid << 3) + (half << 2);      // 4 pairs per half
    const int c4 = lane16 << 2;                      // 4 cols per lane
    const int nchunks = (NND + 127) / 128;           // 782

    for (int chunk = blockIdx.x; chunk < nchunks; chunk += gridDim.x) {
        const int base = chunk * 128;

        ull acc[4][4];
        {
            float4 bv = *(const float4*)&sb[c4];
            #pragma unroll
            for (int i = 0; i < 4; i++) {
                acc[i][0] = pack2(bv.x); acc[i][1] = pack2(bv.y);
                acc[i][2] = pack2(bv.z); acc[i][3] = pack2(bv.w);
            }
        }

        #pragma unroll
        for (int phase = 0; phase < 2; phase++) {
            const float* src = phase ? h : agg;
            const int wofs = phase << 6;             // W rows 0..63 / 64..127
            __syncthreads();                          // buffer safe to overwrite
            #pragma unroll
            for (int it = 0; it < 4; it++) {
                int idx = it * 256 + tid;
                int p  = idx >> 4;
                int kq = (idx & 15) << 2;
                int n0 = base + (p << 1), n1 = n0 + 1;
                float4 a0 = make_float4(0.f, 0.f, 0.f, 0.f);
                float4 a1 = make_float4(0.f, 0.f, 0.f, 0.f);
                if (n0 < NND) a0 = *(const float4*)&src[n0 * HID + kq];
                if (n1 < NND) a1 = *(const float4*)&src[n1 * HID + kq];
                ull* dst = &sAp[p * APSTRIDE1 + kq];
                dst[0] = packf2(a0.x, a1.x);
                dst[1] = packf2(a0.y, a1.y);
                dst[2] = packf2(a0.z, a1.z);
                dst[3] = packf2(a0.w, a1.w);
            }
            __syncthreads();

            #pragma unroll 4
            for (int kb = 0; kb < 64; kb += 2) {
                float4 w0 = *(const float4*)&sW[(wofs + kb) * 64 + c4];
                float4 w1 = *(const float4*)&sW[(wofs + kb + 1) * 64 + c4];
                ull wp0[4] = { pack2(w0.x), pack2(w0.y), pack2(w0.z), pack2(w0.w) };
                ull wp1[4] = { pack2(w1.x), pack2(w1.y), pack2(w1.z), pack2(w1.w) };
                ulonglong2 A[4];
                #pragma unroll
                for (int i = 0; i < 4; i++)
                    A[i] = *(const ulonglong2*)&sAp[(pbase + i) * APSTRIDE1 + kb];
                #pragma unroll
                for (int i = 0; i < 4; i++) {
                    fma2(acc[i][0], A[i].x, wp0[0]); fma2(acc[i][1], A[i].x, wp0[1]);
                    fma2(acc[i][2], A[i].x, wp0[2]); fma2(acc[i][3], A[i].x, wp0[3]);
                    fma2(acc[i][0], A[i].y, wp1[0]); fma2(acc[i][1], A[i].y, wp1[1]);
                    fma2(acc[i][2], A[i].y, wp1[2]); fma2(acc[i][3], A[i].y, wp1[3]);
                }
            }
        }

        #pragma unroll
        for (int i = 0; i < 4; i++) {
            int n0 = base + ((pbase + i) << 1), n1 = n0 + 1;
            float2 v0 = unpk(acc[i][0]), v1 = unpk(acc[i][1]);
            float2 v2 = unpk(acc[i][2]), v3 = unpk(acc[i][3]);
            if (n0 < NND)
                *(float4*)&out[n0 * HID + c4] =
                    make_float4(prelu(v0.x, alpha), prelu(v1.x, alpha),
                                prelu(v2.x, alpha), prelu(v3.x, alpha));
            if (n1 < NND)
                *(float4*)&out[n1 * HID + c4] =
                    make_float4(prelu(v0.y, alpha), prelu(v1.y, alpha),
                                prelu(v2.y, alpha), prelu(v3.y, alpha));
        }
    }
}

// ---------------- single GEMM (K=64), half-warp split, 4 CTAs/SM ------------
__global__ __launch_bounds__(256, 4) void gemm_single_kernel(
    const float* __restrict__ h,
    const float* __restrict__ W, const float* __restrict__ bb,
    float* __restrict__ out)
{
    extern __shared__ float sm[];
    float* sW = sm;                                  // 64*64
    float* sb = sW + 64 * 64;                        // 64
    ull*   sAp = (ull*)(sb + 64);                    // 64 pairs * APSTRIDE1

    const int tid = threadIdx.x;
    #pragma unroll
    for (int t = tid; t < 64 * 16; t += 256) {
        int k = t >> 4, q = (t & 15) << 2;
        *(float4*)&sW[k * 64 + q] = *(const float4*)&W[k * HID + q];
    }
    if (tid < HID) sb[tid] = bb[tid];
    __syncthreads();   // sb/sW visible before any use

    const int lane  = tid & 31;
    const int wid   = tid >> 5;
    const int half  = lane >> 4;
    const int lane16 = lane & 15;
    const int pbase = (wid << 3) + (half << 2);
    const int c4 = lane16 << 2;
    const int nchunks = (NND + 127) / 128;

    for (int chunk = blockIdx.x; chunk < nchunks; chunk += gridDim.x) {
        const int base = chunk * 128;
        __syncthreads();
        #pragma unroll
        for (int it = 0; it < 4; it++) {
            int idx = it * 256 + tid;
            int p  = idx >> 4;
            int kq = (idx & 15) << 2;
            int n0 = base + (p << 1), n1 = n0 + 1;
            float4 a0 = make_float4(0.f, 0.f, 0.f, 0.f);
            float4 a1 = make_float4(0.f, 0.f, 0.f, 0.f);
            if (n0 < NND) a0 = *(const float4*)&h[n0 * HID + kq];
            if (n1 < NND) a1 = *(const float4*)&h[n1 * HID + kq];
            ull* dst = &sAp[p * APSTRIDE1 + kq];
            dst[0] = packf2(a0.x, a1.x);
            dst[1] = packf2(a0.y, a1.y);
            dst[2] = packf2(a0.z, a1.z);
            dst[3] = packf2(a0.w, a1.w);
        }
        __syncthreads();

        ull acc[4][4];
        {
            float4 bv = *(const float4*)&sb[c4];
            #pragma unroll
            for (int i = 0; i < 4; i++) {
                acc[i][0] = pack2(bv.x); acc[i][1] = pack2(bv.y);
                acc[i][2] = pack2(bv.z); acc[i][3] = pack2(bv.w);
            }
        }

        #pragma unroll 4
        for (int kb = 0; kb < 64; kb += 2) {
            float4 w0 = *(const float4*)&sW[kb * 64 + c4];
            float4 w1 = *(const float4*)&sW[(kb + 1) * 64 + c4];
            ull wp0[4] = { pack2(w0.x), pack2(w0.y), pack2(w0.z), pack2(w0.w) };
            ull wp1[4] = { pack2(w1.x), pack2(w1.y), pack2(w1.z), pack2(w1.w) };
            ulonglong2 A[4];
            #pragma unroll
            for (int i = 0; i < 4; i++)
                A[i] = *(const ulonglong2*)&sAp[(pbase + i) * APSTRIDE1 + kb];
            #pragma unroll
            for (int i = 0; i < 4; i++) {
                fma2(acc[i][0], A[i].x, wp0[0]); fma2(acc[i][1], A[i].x, wp0[1]);
                fma2(acc[i][2], A[i].x, wp0[2]); fma2(acc[i][3], A[i].x, wp0[3]);
                fma2(acc[i][0], A[i].y, wp1[0]); fma2(acc[i][1], A[i].y, wp1[1]);
                fma2(acc[i][2], A[i].y, wp1[2]); fma2(acc[i][3], A[i].y, wp1[3]);
            }
        }

        #pragma unroll
        for (int i = 0; i < 4; i++) {
            int n0 = base + ((pbase + i) << 1), n1 = n0 + 1;
            float2 v0 = unpk(acc[i][0]), v1 = unpk(acc[i][1]);
            float2 v2 = unpk(acc[i][2]), v3 = unpk(acc[i][3]);
            if (n0 < NND)
                *(float4*)&out[n0 * HID + c4] = make_float4(v0.x, v1.x, v2.x, v3.x);
            if (n1 < NND)
                *(float4*)&out[n1 * HID + c4] = make_float4(v0.y, v1.y, v2.y, v3.y);
        }
    }
}

// ---------------- launch -----------------------------------------------------
extern "C" void kernel_launch(void* const* d_in, const int* in_sizes, int n_in,
                              void* d_out, int out_size) {
    const int*   x    = (const int*)d_in[0];
    const int*   ei   = (const int*)d_in[1];
    // d_in[2] = edge_weight : unused by the reference
    const float* emb  = (const float*)d_in[3];
    const float* Wl1  = (const float*)d_in[4];
    const float* bl1  = (const float*)d_in[5];
    const float* Wr1  = (const float*)d_in[6];
    const float* a1   = (const float*)d_in[7];
    const float* Wl2  = (const float*)d_in[8];
    const float* bl2  = (const float*)d_in[9];
    const float* Wr2  = (const float*)d_in[10];
    const float* a2   = (const float*)d_in[11];
    const float* Wout = (const float*)d_in[12];
    const float* bout = (const float*)d_in[13];
    float* out = (float*)d_out;

    float *h0, *h1, *agg;
    cudaGetSymbolAddress((void**)&h0,  g_h0);
    cudaGetSymbolAddress((void**)&h1,  g_h1);
    cudaGetSymbolAddress((void**)&agg, g_agg);

    const size_t smem_dual   = (128 * 64 + 64) * sizeof(float) + 64 * APSTRIDE1 * sizeof(ull); // ~67KB
    const size_t smem_single = (64 * 64 + 64)  * sizeof(float) + 64 * APSTRIDE1 * sizeof(ull); // ~50KB
    cudaFuncSetAttribute(gemm_dual_kernel,
                         cudaFuncAttributeMaxDynamicSharedMemorySize, (int)smem_dual);
    cudaFuncSetAttribute(gemm_single_kernel,
                         cudaFuncAttributeMaxDynamicSharedMemorySize, (int)smem_single);

    const int g_agg_grid = (NND * 16) / 256;   // 6250

    prep_kernel<<<g_agg_grid, 256>>>(x, emb, h0);
    count_kernel<<<(NE + 255) / 256, 256>>>(ei);
    csr_kernel<<<CSR_BLOCKS, CSR_THREADS>>>(ei);

    // layer 1
    agg_kernel<<<g_agg_grid, 256>>>(h0, agg);
    gemm_dual_kernel<<<444, 256, smem_dual>>>(h0, agg, Wl1, bl1, Wr1, a1, h1);

    // layer 2
    agg_kernel<<<g_agg_grid, 256>>>(h1, agg);
    gemm_dual_kernel<<<444, 256, smem_dual>>>(h1, agg, Wl2, bl2, Wr2, a2, h0);

    // output projection
    gemm_single_kernel<<<592, 256, smem_single>>>(h0, Wout, bout, out);
}